// round 13
// baseline (speedup 1.0000x reference)
#include <cuda_runtime.h>
#include <math.h>

#define NPT 3000
#define BB 2
#define CCH 128
#define CH 64
#define LL 6
#define EPSBN 1e-5f
#define ATT_SCALE 0.08838834764831845f  // 1/sqrt(128)

#define TQ 64
#define TI 128
#define ISPLIT 3
#define SPLEN 1000
#define OPAD 3008
#define NEGBIG -1e30f

typedef unsigned long long ull;

__device__ __forceinline__ void ffma2(ull &d, ull a, ull b) {
    asm("fma.rn.f32x2 %0, %1, %2, %0;" : "+l"(d) : "l"(a), "l"(b));
}
__device__ __forceinline__ void mulf2(ull &d, ull f) {
    asm("mul.rn.f32x2 %0, %0, %1;" : "+l"(d) : "l"(f));
}
__device__ __forceinline__ float2 unp(ull v) {
    unsigned lo, hi;
    asm("mov.b64 {%0,%1}, %2;" : "=r"(lo), "=r"(hi) : "l"(v));
    return make_float2(__uint_as_float(lo), __uint_as_float(hi));
}
__device__ __forceinline__ ull packdup(float x) {
    ull r; unsigned u = __float_as_uint(x);
    asm("mov.b64 %0, {%1, %1};" : "=l"(r) : "r"(u));
    return r;
}
__device__ __forceinline__ ull d2u(double d) { return __double_as_longlong(d); }
__device__ __forceinline__ float sqrt_approx(float x) {
    float r; asm("sqrt.approx.f32 %0, %1;" : "=f"(r) : "f"(x)); return r;
}

// ---------------- device scratch ----------------
__device__ float g_x[BB*CCH*NPT];
__device__ float g_y[BB*CCH*NPT];
__device__ float g_v[BB*CCH*NPT];
__device__ float g_m[BB*CCH*NPT];
__device__ float g_h[BB*CCH*NPT];
__device__ float g_qt[(size_t)BB*NPT*CCH];
__device__ float g_kt[(size_t)BB*NPT*CCH];
__device__ float g_Op[(size_t)ISPLIT*BB*CCH*OPAD];
__device__ float g_Lp[ISPLIT*BB*OPAD];
__device__ float g_Mm[ISPLIT*BB*OPAD];
__device__ float g_ps[CCH*128], g_pq[CCH*128];
__device__ float g_scl[CCH],  g_shf[CCH];
__device__ float g_scl1[CCH], g_shf1[CCH];
__device__ float g_scl2[CCH], g_shf2[CCH];

// ---------------- init embedding ----------------
__global__ void init_conv_kernel(const float* __restrict__ corr, const float* __restrict__ W,
                                 const float* __restrict__ bias, float* __restrict__ X)
{
    __shared__ float Ws[CCH*6];
    __shared__ float bs[CCH];
    int tid = threadIdx.x;
    for (int i = tid; i < CCH*6; i += blockDim.x) Ws[i] = W[i];
    for (int i = tid; i < CCH;   i += blockDim.x) bs[i] = bias[i];
    __syncthreads();
    int idx = blockIdx.x * blockDim.x + tid;
    if (idx >= BB*NPT) return;
    int b = idx / NPT, n = idx - b*NPT;
    float cp[6];
#pragma unroll
    for (int j = 0; j < 6; j++) cp[j] = corr[(size_t)idx*6 + j];
    for (int co = 0; co < CCH; co++) {
        float a = bs[co];
#pragma unroll
        for (int j = 0; j < 6; j++) a += Ws[co*6 + j] * cp[j];
        X[((size_t)b*CCH + co)*NPT + n] = a;
    }
}

// ---------------- conv smem: 64 co x 64 n tile, full CIN ----------------
template<int CIN> struct ConvS {
    float Xs[64][CIN + 4];   // [n][ci], stride ≡ 4 mod 32 -> conflict-free
    float Ws[64][CIN + 4];   // [co][ci]
    float sA[CCH], sB[CCH];
    float swc[ISPLIT][64];
};

// ---------------- pointwise conv (8co broadcast x 2n per warp) ----------------
// INMODE: 0 plain, 1 relu(scl*x+shf) on input, 3 weighted 3-way Op merge (Mm/Lp via rscl/rshf)
// RES:    0 none, 2 add relu(rscl*R+rshf)
template<int CIN, int INMODE, int RES, bool STATS>
__global__ void __launch_bounds__(256, 2) conv_kernel(const float* __restrict__ X,
        const float* __restrict__ W, const float* __restrict__ bias,
        const float* __restrict__ scl, const float* __restrict__ shf,
        const float* __restrict__ R, const float* __restrict__ rscl,
        const float* __restrict__ rshf,
        float* __restrict__ Y, float* __restrict__ psum, float* __restrict__ psq,
        int Cout)
{
    extern __shared__ char sraw[];
    ConvS<CIN>& S = *reinterpret_cast<ConvS<CIN>*>(sraw);
    const int tid = threadIdx.x;
    const int b = blockIdx.z, co0 = blockIdx.y << 6, n0 = blockIdx.x << 6;

    if (INMODE == 1) {
        if (tid < CIN) { S.sA[tid] = scl[tid]; S.sB[tid] = shf[tid]; }
    }
    if (INMODE == 3) {
        if (tid < 64) {
            int n = n0 + tid;
            float w0 = 0.f, w1 = 0.f, w2 = 0.f;
            if (n < NPT) {
                float m0 = rscl[(0*BB + b)*OPAD + n];
                float m1v = rscl[(1*BB + b)*OPAD + n];
                float m2v = rscl[(2*BB + b)*OPAD + n];
                float l0 = rshf[(0*BB + b)*OPAD + n];
                float l1 = rshf[(1*BB + b)*OPAD + n];
                float l2 = rshf[(2*BB + b)*OPAD + n];
                float Mx = fmaxf(fmaxf(m0, m1v), m2v);
                w0 = __expf(m0 - Mx); w1 = __expf(m1v - Mx); w2 = __expf(m2v - Mx);
                float inv = 1.f / (l0*w0 + l1*w1 + l2*w2);
                w0 *= inv; w1 *= inv; w2 *= inv;
            }
            S.swc[0][tid] = w0; S.swc[1][tid] = w1; S.swc[2][tid] = w2;
        }
    }
    if (INMODE != 0) __syncthreads();

    // ---- W tile fill [64][CIN] ----
#pragma unroll
    for (int j = 0; j < 64*CIN/1024; j++) {
        int idx = tid + (j << 8);
        int row = idx / (CIN/4), c4 = (idx % (CIN/4)) << 2;
        *(float4*)&S.Ws[row][c4] = *(const float4*)&W[(size_t)(co0 + row)*CIN + c4];
    }
    // ---- X tile fill [64 n][CIN], transposed (lanes->ci: conflict-free STS) ----
#pragma unroll
    for (int j = 0; j < 64*CIN/1024; j++) {
        int idx = tid + (j << 8);
        int ci = idx & (CIN - 1);
        int n4 = (idx / CIN) << 2;
        float4 v = make_float4(0.f,0.f,0.f,0.f);
        if (n0 + n4 < NPT) {
            if (INMODE == 3) {
                const size_t sstr = (size_t)BB*CCH*OPAD;
                const float* base = X + ((size_t)(b*CCH + ci))*OPAD + n0 + n4;
                float4 a0 = *(const float4*)&base[0];
                float4 a1 = *(const float4*)&base[sstr];
                float4 a2 = *(const float4*)&base[2*sstr];
                v.x = a0.x*S.swc[0][n4]   + a1.x*S.swc[1][n4]   + a2.x*S.swc[2][n4];
                v.y = a0.y*S.swc[0][n4+1] + a1.y*S.swc[1][n4+1] + a2.y*S.swc[2][n4+1];
                v.z = a0.z*S.swc[0][n4+2] + a1.z*S.swc[1][n4+2] + a2.z*S.swc[2][n4+2];
                v.w = a0.w*S.swc[0][n4+3] + a1.w*S.swc[1][n4+3] + a2.w*S.swc[2][n4+3];
            } else {
                v = *(const float4*)&X[((size_t)(b*CIN + ci))*NPT + n0 + n4];
                if (INMODE == 1) {
                    float sa = S.sA[ci], sb = S.sB[ci];
                    v.x = fmaxf(fmaf(sa, v.x, sb), 0.f);
                    v.y = fmaxf(fmaf(sa, v.y, sb), 0.f);
                    v.z = fmaxf(fmaf(sa, v.z, sb), 0.f);
                    v.w = fmaxf(fmaf(sa, v.w, sb), 0.f);
                }
            }
        }
        S.Xs[n4][ci] = v.x; S.Xs[n4+1][ci] = v.y;
        S.Xs[n4+2][ci] = v.z; S.Xs[n4+3][ci] = v.w;
    }
    __syncthreads();

    const int warp = tid >> 5, lane = tid & 31;
    const int r0 = warp << 3;        // 8 co per warp
    ull acc[8][2];
#pragma unroll
    for (int r = 0; r < 8; r++) { acc[r][0] = 0ull; acc[r][1] = 0ull; }

#pragma unroll 8
    for (int cq = 0; cq < CIN; cq += 4) {
        double2 xv0 = *(const double2*)&S.Xs[lane][cq];
        double2 xv1 = *(const double2*)&S.Xs[lane + 32][cq];
        ull x0a = d2u(xv0.x), x0b = d2u(xv0.y);
        ull x1a = d2u(xv1.x), x1b = d2u(xv1.y);
#pragma unroll
        for (int r = 0; r < 8; r++) {
            double2 wv = *(const double2*)&S.Ws[r0 + r][cq];
            ull ax = d2u(wv.x), ay = d2u(wv.y);
            ffma2(acc[r][0], ax, x0a);
            ffma2(acc[r][0], ay, x0b);
            ffma2(acc[r][1], ax, x1a);
            ffma2(acc[r][1], ay, x1b);
        }
    }

    float vals[8][2];
#pragma unroll
    for (int r = 0; r < 8; r++) {
        float bv = bias[co0 + r0 + r];
#pragma unroll
        for (int s = 0; s < 2; s++) {
            float2 f = unp(acc[r][s]);
            vals[r][s] = f.x + f.y + bv;
        }
    }

    if (STATS) {
#pragma unroll
        for (int r = 0; r < 8; r++) {
            float s_ = 0.f, sq = 0.f;
#pragma unroll
            for (int s = 0; s < 2; s++) {
                int n = n0 + lane + (s << 5);
                if (n < NPT) { s_ += vals[r][s]; sq += vals[r][s]*vals[r][s]; }
            }
#pragma unroll
            for (int o = 16; o; o >>= 1) {
                s_ += __shfl_xor_sync(0xffffffffu, s_, o);
                sq += __shfl_xor_sync(0xffffffffu, sq, o);
            }
            if (lane == 0) {
                int co = co0 + r0 + r;
                int p = b*47 + blockIdx.x;     // 94 partials
                psum[co*128 + p] = s_;
                psq[co*128 + p]  = sq;
            }
        }
    }

#pragma unroll
    for (int s = 0; s < 2; s++) {
        int n = n0 + lane + (s << 5);
        if (n >= NPT) continue;
#pragma unroll
        for (int r = 0; r < 8; r++) {
            int co = co0 + r0 + r;
            float v = vals[r][s];
            size_t off = ((size_t)(b*Cout + co))*NPT + n;
            if (RES == 2) {
                float rr = R[off];
                v += fmaxf(fmaf(rscl[co], rr, rshf[co]), 0.f);
            }
            Y[off] = v;
        }
    }
}

// ---------------- fused q/k/v conv (same 64x64 tiling) ----------------
__global__ void __launch_bounds__(256, 2) qkv_kernel(const float* __restrict__ X,
        const float* __restrict__ qW, const float* __restrict__ kW, const float* __restrict__ vW,
        const float* __restrict__ qb, const float* __restrict__ kb, const float* __restrict__ vb,
        const float* __restrict__ scl, const float* __restrict__ shf,
        float* __restrict__ qt, float* __restrict__ kt, float* __restrict__ v)
{
    extern __shared__ char sraw[];
    ConvS<CCH>& S = *reinterpret_cast<ConvS<CCH>*>(sraw);
    const int tid = threadIdx.x;
    const int sel = blockIdx.y >> 1;
    const float* W    = (sel == 0) ? qW : (sel == 1) ? kW : vW;
    const float* bias = (sel == 0) ? qb : (sel == 1) ? kb : vb;
    const int b = blockIdx.z, co0 = (blockIdx.y & 1) << 6, n0 = blockIdx.x << 6;

    if (tid < CCH) { S.sA[tid] = scl[tid]; S.sB[tid] = shf[tid]; }
    __syncthreads();

#pragma unroll
    for (int j = 0; j < 8; j++) {
        int idx = tid + (j << 8);
        int row = idx >> 5, c4 = (idx & 31) << 2;
        *(float4*)&S.Ws[row][c4] = *(const float4*)&W[(size_t)(co0 + row)*CCH + c4];
    }
#pragma unroll
    for (int j = 0; j < 8; j++) {
        int idx = tid + (j << 8);
        int ci = idx & 127;
        int n4 = (idx >> 7) << 2;
        float4 vv = make_float4(0.f,0.f,0.f,0.f);
        if (n0 + n4 < NPT) {
            vv = *(const float4*)&X[((size_t)(b*CCH + ci))*NPT + n0 + n4];
            float sa = S.sA[ci], sb = S.sB[ci];
            vv.x = fmaxf(fmaf(sa, vv.x, sb), 0.f);
            vv.y = fmaxf(fmaf(sa, vv.y, sb), 0.f);
            vv.z = fmaxf(fmaf(sa, vv.z, sb), 0.f);
            vv.w = fmaxf(fmaf(sa, vv.w, sb), 0.f);
        }
        S.Xs[n4][ci] = vv.x; S.Xs[n4+1][ci] = vv.y;
        S.Xs[n4+2][ci] = vv.z; S.Xs[n4+3][ci] = vv.w;
    }
    __syncthreads();

    const int warp = tid >> 5, lane = tid & 31;
    const int r0 = warp << 3;
    ull acc[8][2];
#pragma unroll
    for (int r = 0; r < 8; r++) { acc[r][0] = 0ull; acc[r][1] = 0ull; }

#pragma unroll 8
    for (int cq = 0; cq < CCH; cq += 4) {
        double2 xv0 = *(const double2*)&S.Xs[lane][cq];
        double2 xv1 = *(const double2*)&S.Xs[lane + 32][cq];
        ull x0a = d2u(xv0.x), x0b = d2u(xv0.y);
        ull x1a = d2u(xv1.x), x1b = d2u(xv1.y);
#pragma unroll
        for (int r = 0; r < 8; r++) {
            double2 wv = *(const double2*)&S.Ws[r0 + r][cq];
            ull ax = d2u(wv.x), ay = d2u(wv.y);
            ffma2(acc[r][0], ax, x0a);
            ffma2(acc[r][0], ay, x0b);
            ffma2(acc[r][1], ax, x1a);
            ffma2(acc[r][1], ay, x1b);
        }
    }

    float vals[8][2];
#pragma unroll
    for (int r = 0; r < 8; r++) {
        float bv = bias[co0 + r0 + r];
#pragma unroll
        for (int s = 0; s < 2; s++) {
            float2 f = unp(acc[r][s]);
            vals[r][s] = f.x + f.y + bv;
        }
    }

    if (sel < 2) {
        float* base = ((sel == 0) ? qt : kt) + (size_t)b*NPT*CCH;
#pragma unroll
        for (int s = 0; s < 2; s++) {
            int n = n0 + lane + (s << 5);
            if (n >= NPT) continue;
            *(float4*)&base[(size_t)n*CCH + co0 + r0] =
                make_float4(vals[0][s], vals[1][s], vals[2][s], vals[3][s]);
            *(float4*)&base[(size_t)n*CCH + co0 + r0 + 4] =
                make_float4(vals[4][s], vals[5][s], vals[6][s], vals[7][s]);
        }
    } else {
#pragma unroll
        for (int s = 0; s < 2; s++) {
            int n = n0 + lane + (s << 5);
            if (n >= NPT) continue;
#pragma unroll
            for (int r = 0; r < 8; r++)
                v[((size_t)(b*CCH + co0 + r0 + r))*NPT + n] = vals[r][s];
        }
    }
}

// ---------------- partial-sum reduce -> per-channel affine ----------------
__global__ void bnred_kernel(const float* __restrict__ psum, const float* __restrict__ psq,
                             const float* __restrict__ g, const float* __restrict__ beta,
                             float* __restrict__ scl, float* __restrict__ shf)
{
    int c = blockIdx.x, t = threadIdx.x;
    float s = 0.f, q = 0.f;
    for (int p = t; p < 94; p += 32) { s += psum[c*128 + p]; q += psq[c*128 + p]; }
#pragma unroll
    for (int o = 16; o; o >>= 1) {
        s += __shfl_xor_sync(0xffffffffu, s, o);
        q += __shfl_xor_sync(0xffffffffu, q, o);
    }
    if (t == 0) {
        float inv = 1.f / (float)(BB*NPT);
        float m = s * inv;
        float var = q * inv - m*m;
        float rs = rsqrtf(var + EPSBN);
        scl[c] = g[c] * rs;
        shf[c] = beta[c] - m * g[c] * rs;
    }
}

// ---------------- flash attention (unchanged, proven) ----------------
struct FlashS {
    float Qt[TQ][132];
    float KV[CCH*132];
    float Pd[TQ][132];
    float pOs[TQ][6];
    float pI[TI][6];
    float alph[TQ];
};

__global__ void __launch_bounds__(512, 1) flash_kernel(
    const float* __restrict__ Qt, const float* __restrict__ Kt,
    const float* __restrict__ V,
    const float* __restrict__ src, const float* __restrict__ tgt,
    float* __restrict__ Op, float* __restrict__ Lp, float* __restrict__ Mm)
{
    extern __shared__ char smem_raw[];
    FlashS& S = *reinterpret_cast<FlashS*>(smem_raw);
    int tid = threadIdx.x;
    int otile = blockIdx.x * TQ;
    int sp = blockIdx.y, b = blockIdx.z;
    int sbase = sp * SPLEN;
    int send  = min(sbase + SPLEN, NPT);
    int warp = tid >> 5, lane = tid & 31;
    int o0 = warp << 2;
    int c0 = warp << 3;

#pragma unroll
    for (int j = 0; j < 4; j++) {
        int idx = tid + (j << 9);
        int row = idx >> 5, c4 = (idx & 31) << 2;
        int go = otile + row;
        float4 qv = make_float4(0.f,0.f,0.f,0.f);
        if (go < NPT) qv = *(const float4*)&Qt[((size_t)b*NPT + go)*CCH + c4];
        *(float4*)&S.Qt[row][c4] = qv;
    }
    if (tid < TQ) {
        int go = otile + tid;
        if (go < NPT) {
#pragma unroll
            for (int e = 0; e < 3; e++) {
                S.pOs[tid][e]   = src[((size_t)b*NPT + go)*3 + e];
                S.pOs[tid][3+e] = tgt[((size_t)b*NPT + go)*3 + e];
            }
        } else {
#pragma unroll
            for (int e = 0; e < 6; e++) S.pOs[tid][e] = 0.f;
        }
    }
    float mr[4] = {NEGBIG, NEGBIG, NEGBIG, NEGBIG};
    float lr[4] = {0.f, 0.f, 0.f, 0.f};
    ull accO[8][2];
#pragma unroll
    for (int i = 0; i < 8; i++) { accO[i][0] = 0ull; accO[i][1] = 0ull; }

    const int nch = (send - sbase + TI - 1) / TI;
#pragma unroll 1
    for (int ch = 0; ch < nch; ch++) {
        int ibase = sbase + ch * TI;
        __syncthreads();
#pragma unroll
        for (int j = 0; j < 8; j++) {
            int idx = tid + (j << 9);
            int row = idx >> 5, c4 = (idx & 31) << 2;
            int gi = ibase + row;
            float4 kv = make_float4(0.f,0.f,0.f,0.f);
            if (gi < send) kv = *(const float4*)&Kt[((size_t)b*NPT + gi)*CCH + c4];
            *(float4*)&S.KV[row*132 + c4] = kv;
        }
        if (tid < TI) {
            int gi = ibase + tid;
            if (gi < send) {
#pragma unroll
                for (int e = 0; e < 3; e++) {
                    S.pI[tid][e]   = src[((size_t)b*NPT + gi)*3 + e];
                    S.pI[tid][3+e] = tgt[((size_t)b*NPT + gi)*3 + e];
                }
            } else {
#pragma unroll
                for (int e = 0; e < 6; e++) S.pI[tid][e] = 0.f;
            }
        }
        __syncthreads();

        ull sacc[4][4];
#pragma unroll
        for (int r = 0; r < 4; r++)
#pragma unroll
            for (int s = 0; s < 4; s++) sacc[r][s] = 0ull;
#pragma unroll 4
        for (int cq = 0; cq < CCH; cq += 4) {
            double2 qv[4], kv[4];
#pragma unroll
            for (int r = 0; r < 4; r++) qv[r] = *(const double2*)&S.Qt[o0 + r][cq];
#pragma unroll
            for (int s = 0; s < 4; s++) kv[s] = *(const double2*)&S.KV[(lane + (s << 5))*132 + cq];
#pragma unroll
            for (int r = 0; r < 4; r++) {
                ull ax = d2u(qv[r].x), ay = d2u(qv[r].y);
#pragma unroll
                for (int s = 0; s < 4; s++) {
                    ffma2(sacc[r][s], ax, d2u(kv[s].x));
                    ffma2(sacc[r][s], ay, d2u(kv[s].y));
                }
            }
        }

        float sv[4][4];
#pragma unroll
        for (int r = 0; r < 4; r++)
#pragma unroll
            for (int s = 0; s < 4; s++) {
                float2 f = unp(sacc[r][s]);
                sv[r][s] = f.x + f.y;
            }
#pragma unroll
        for (int s = 0; s < 4; s++) {
            int il = lane + (s << 5);
            bool valid = (ibase + il) < send;
            float pi0 = S.pI[il][0], pi1 = S.pI[il][1], pi2 = S.pI[il][2];
            float pi3 = S.pI[il][3], pi4 = S.pI[il][4], pi5 = S.pI[il][5];
#pragma unroll
            for (int r = 0; r < 4; r++) {
                float dx = S.pOs[o0+r][0] - pi0, dy = S.pOs[o0+r][1] - pi1, dz = S.pOs[o0+r][2] - pi2;
                float ds = sqrt_approx(dx*dx + dy*dy + dz*dz);
                dx = S.pOs[o0+r][3] - pi3; dy = S.pOs[o0+r][4] - pi4; dz = S.pOs[o0+r][5] - pi5;
                float dt = sqrt_approx(dx*dx + dy*dy + dz*dz);
                float d = ds - dt;
                float scv = fmaxf(1.f - d*d, 0.f) * ATT_SCALE;
                sv[r][s] = valid ? sv[r][s] * scv : NEGBIG;
            }
        }
#pragma unroll
        for (int r = 0; r < 4; r++) {
            float mx = fmaxf(fmaxf(sv[r][0], sv[r][1]), fmaxf(sv[r][2], sv[r][3]));
#pragma unroll
            for (int s = 16; s; s >>= 1) mx = fmaxf(mx, __shfl_xor_sync(0xffffffffu, mx, s));
            float mnew = fmaxf(mr[r], mx);
            float al = __expf(mr[r] - mnew);
            mr[r] = mnew;
            float psum = 0.f;
#pragma unroll
            for (int s = 0; s < 4; s++) {
                float p = __expf(sv[r][s] - mnew);
                S.Pd[o0 + r][lane + (s << 5)] = p;
                psum += p;
            }
#pragma unroll
            for (int s = 16; s; s >>= 1) psum += __shfl_xor_sync(0xffffffffu, psum, s);
            lr[r] = lr[r] * al + psum;
            if (lane == 0) S.alph[o0 + r] = al;
        }
        __syncthreads();

#pragma unroll
        for (int j = 0; j < 8; j++) {
            int idx = tid + (j << 9);
            int row = idx >> 5, i4 = (idx & 31) << 2;
            int gi = ibase + i4;
            float4 vv = make_float4(0.f,0.f,0.f,0.f);
            if (gi < send) vv = *(const float4*)&V[((size_t)(b*CCH + row))*NPT + gi];
            *(float4*)&S.KV[row*132 + i4] = vv;
        }
        __syncthreads();

        {
            ull ad0 = packdup(S.alph[lane]);
            ull ad1 = packdup(S.alph[lane + 32]);
#pragma unroll
            for (int cc = 0; cc < 8; cc++) { mulf2(accO[cc][0], ad0); mulf2(accO[cc][1], ad1); }
        }
#pragma unroll 2
        for (int iq = 0; iq < TI; iq += 4) {
            double2 b0 = *(const double2*)&S.Pd[lane][iq];
            double2 b1 = *(const double2*)&S.Pd[lane + 32][iq];
            ull b0x = d2u(b0.x), b0y = d2u(b0.y), b1x = d2u(b1.x), b1y = d2u(b1.y);
#pragma unroll
            for (int cc = 0; cc < 8; cc++) {
                double2 av = *(const double2*)&S.KV[(c0 + cc)*132 + iq];
                ull ax = d2u(av.x), ay = d2u(av.y);
                ffma2(accO[cc][0], ax, b0x);
                ffma2(accO[cc][0], ay, b0y);
                ffma2(accO[cc][1], ax, b1x);
                ffma2(accO[cc][1], ay, b1y);
            }
        }
    }

#pragma unroll
    for (int cc = 0; cc < 8; cc++)
#pragma unroll
        for (int ok = 0; ok < 2; ok++) {
            float2 f = unp(accO[cc][ok]);
            float val = f.x + f.y;
            int go = otile + lane + (ok << 5);
            if (go < NPT)
                Op[((size_t)((sp*BB + b)*CCH + c0 + cc))*OPAD + go] = val;
        }
    if (lane == 0) {
#pragma unroll
        for (int r = 0; r < 4; r++) {
            int go = otile + o0 + r;
            if (go < NPT) {
                Mm[(sp*BB + b)*OPAD + go] = mr[r];
                Lp[(sp*BB + b)*OPAD + go] = lr[r];
            }
        }
    }
}

// ---------------- fused head: norm + c1 + c2 + c3 ----------------
struct HeadS {
    float xt[CCH][68];
    float cw1[32][128];
    float cw2[32][32];
    float cw3[32];
    float b1[32], b2[32];
    float ph1[64][33];
    float ph2[64][33];
    float sinv[64];
};

__global__ void __launch_bounds__(256) head_kernel(const float* __restrict__ X,
        const float* __restrict__ c1W, const float* __restrict__ c1b,
        const float* __restrict__ c2W, const float* __restrict__ c2b,
        const float* __restrict__ c3W, const float* __restrict__ c3b,
        float* __restrict__ out)
{
    extern __shared__ char sraw[];
    HeadS& S = *reinterpret_cast<HeadS*>(sraw);
    int tid = threadIdx.x;
    int n0 = blockIdx.x << 6, b = blockIdx.y;

    for (int i = tid; i < 32*128; i += 256) S.cw1[i >> 7][i & 127] = c1W[i];
    for (int i = tid; i < 32*32;  i += 256) S.cw2[i >> 5][i & 31]  = c2W[i];
    if (tid < 32) { S.cw3[tid] = c3W[tid]; S.b1[tid] = c1b[tid]; S.b2[tid] = c2b[tid]; }
    for (int t = tid; t < CCH*16; t += 256) {
        int row = t >> 4, j4 = (t & 15) << 2;
        float4 v = make_float4(0.f,0.f,0.f,0.f);
        if (n0 + j4 < NPT) v = *(const float4*)&X[((size_t)(b*CCH + row))*NPT + n0 + j4];
        *(float4*)&S.xt[row][j4] = v;
    }
    __syncthreads();

    int p = tid >> 2, qd = tid & 3;
    float ss = 0.f;
    for (int c = qd*32; c < qd*32 + 32; c++) { float v = S.xt[c][p]; ss += v*v; }
    ss += __shfl_xor_sync(0xffffffffu, ss, 1, 4);
    ss += __shfl_xor_sync(0xffffffffu, ss, 2, 4);
    if (qd == 0) S.sinv[p] = 1.f / fmaxf(sqrtf(ss), 1e-12f);

#pragma unroll
    for (int jj = 0; jj < 8; jj++) {
        int j = qd*8 + jj;
        float a = S.b1[j];
        for (int c = 0; c < CCH; c++) a += S.cw1[j][c] * S.xt[c][p];
        S.ph1[p][j] = fmaxf(a, 0.f);
    }
    __syncthreads();
#pragma unroll
    for (int jj = 0; jj < 8; jj++) {
        int j = qd*8 + jj;
        float a = S.b2[j];
        for (int c = 0; c < 32; c++) a += S.cw2[j][c] * S.ph1[p][c];
        S.ph2[p][j] = fmaxf(a, 0.f);
    }
    __syncthreads();
    if (qd == 0) {
        float a = c3b[0];
        for (int c = 0; c < 32; c++) a += S.cw3[c] * S.ph2[p][c];
        int n = n0 + p;
        if (n < NPT) out[b*NPT + n] = a;
    }
    float* dst = out + BB*NPT;
    for (int t = tid; t < CCH*16; t += 256) {
        int row = t >> 4, j4 = (t & 15) << 2;
#pragma unroll
        for (int e = 0; e < 4; e++) {
            int n = n0 + j4 + e;
            if (n < NPT)
                dst[((size_t)(b*CCH + row))*NPT + n] = S.xt[row][j4 + e] * S.sinv[j4 + e];
        }
    }
}

// ======================= host launcher =======================
extern "C" void kernel_launch(void* const* d_in, const int* in_sizes, int n_in,
                              void* d_out, int out_size)
{
    const float* corr    = (const float*)d_in[0];
    const float* src     = (const float*)d_in[1];
    const float* tgt     = (const float*)d_in[2];
    const float* iW      = (const float*)d_in[3];
    const float* ib      = (const float*)d_in[4];
    const float* pcnW    = (const float*)d_in[5];
    const float* pcnb    = (const float*)d_in[6];
    const float* pcng    = (const float*)d_in[7];
    const float* pcnbeta = (const float*)d_in[8];
    const float* qW  = (const float*)d_in[9];  const float* qb  = (const float*)d_in[10];
    const float* kW  = (const float*)d_in[11]; const float* kb  = (const float*)d_in[12];
    const float* vW  = (const float*)d_in[13]; const float* vb  = (const float*)d_in[14];
    const float* m1W = (const float*)d_in[15]; const float* m1b = (const float*)d_in[16];
    const float* m1g = (const float*)d_in[17]; const float* m1beta = (const float*)d_in[18];
    const float* m2W = (const float*)d_in[19]; const float* m2b = (const float*)d_in[20];
    const float* m2g = (const float*)d_in[21]; const float* m2beta = (const float*)d_in[22];
    const float* m3W = (const float*)d_in[23]; const float* m3b = (const float*)d_in[24];
    const float* c1W = (const float*)d_in[25]; const float* c1b = (const float*)d_in[26];
    const float* c2W = (const float*)d_in[27]; const float* c2b = (const float*)d_in[28];
    const float* c3W = (const float*)d_in[29]; const float* c3b = (const float*)d_in[30];
    float* out = (float*)d_out;

    float *x, *y, *v, *m, *h, *qt, *kt, *Op, *Lp, *Mm, *ps, *pq;
    float *scl, *shf, *scl1, *shf1, *scl2, *shf2;
    cudaGetSymbolAddress((void**)&x,  g_x);
    cudaGetSymbolAddress((void**)&y,  g_y);
    cudaGetSymbolAddress((void**)&v,  g_v);
    cudaGetSymbolAddress((void**)&m,  g_m);
    cudaGetSymbolAddress((void**)&h,  g_h);
    cudaGetSymbolAddress((void**)&qt, g_qt);
    cudaGetSymbolAddress((void**)&kt, g_kt);
    cudaGetSymbolAddress((void**)&Op, g_Op);
    cudaGetSymbolAddress((void**)&Lp, g_Lp);
    cudaGetSymbolAddress((void**)&Mm, g_Mm);
    cudaGetSymbolAddress((void**)&ps, g_ps);
    cudaGetSymbolAddress((void**)&pq, g_pq);
    cudaGetSymbolAddress((void**)&scl,  g_scl);  cudaGetSymbolAddress((void**)&shf,  g_shf);
    cudaGetSymbolAddress((void**)&scl1, g_scl1); cudaGetSymbolAddress((void**)&shf1, g_shf1);
    cudaGetSymbolAddress((void**)&scl2, g_scl2); cudaGetSymbolAddress((void**)&shf2, g_shf2);

    const int nT64 = (NPT + 63) / 64;    // 47
    const int smemC128 = (int)sizeof(ConvS<128>);
    const int smemC64  = (int)sizeof(ConvS<64>);
    const int smemFlash = (int)sizeof(FlashS);
    const int smemHead  = (int)sizeof(HeadS);
    cudaFuncSetAttribute(conv_kernel<128,0,0,true>, cudaFuncAttributeMaxDynamicSharedMemorySize, smemC128);
    cudaFuncSetAttribute(conv_kernel<128,3,0,true>, cudaFuncAttributeMaxDynamicSharedMemorySize, smemC128);
    cudaFuncSetAttribute(conv_kernel<64,1,0,true>,  cudaFuncAttributeMaxDynamicSharedMemorySize, smemC64);
    cudaFuncSetAttribute(conv_kernel<64,1,2,false>, cudaFuncAttributeMaxDynamicSharedMemorySize, smemC64);
    cudaFuncSetAttribute(qkv_kernel, cudaFuncAttributeMaxDynamicSharedMemorySize, smemC128);
    cudaFuncSetAttribute(flash_kernel, cudaFuncAttributeMaxDynamicSharedMemorySize, smemFlash);
    cudaFuncSetAttribute(head_kernel,  cudaFuncAttributeMaxDynamicSharedMemorySize, smemHead);

    dim3 blk(256);
    init_conv_kernel<<<(BB*NPT + 127)/128, 128>>>(corr, iW, ib, x);

    for (int l = 0; l < LL; l++) {
        // PointCN conv (pre-BN output y) + stats partials
        conv_kernel<128,0,0,true><<<dim3(nT64,2,BB), blk, smemC128>>>(
            x, pcnW + (size_t)l*CCH*CCH, pcnb + l*CCH,
            nullptr, nullptr, nullptr, nullptr, nullptr,
            y, ps, pq, CCH);
        bnred_kernel<<<CCH, 32>>>(ps, pq, pcng + l*CCH, pcnbeta + l*CCH, scl, shf);

        // fused q/k/v (564 blocks; affine+relu on load; q,k transposed out)
        qkv_kernel<<<dim3(nT64,6,BB), blk, smemC128>>>(
            y, qW + (size_t)l*CCH*CCH, kW + (size_t)l*CCH*CCH, vW + (size_t)l*CCH*CCH,
            qb + l*CCH, kb + l*CCH, vb + l*CCH, scl, shf, qt, kt, v);

        // flash attention
        flash_kernel<<<dim3(nT64, ISPLIT, BB), 512, smemFlash>>>(qt, kt, v, src, tgt, Op, Lp, Mm);

        // m1: merge partials on load (weights from Mm/Lp), stats out
        conv_kernel<128,3,0,true><<<dim3(nT64,1,BB), blk, smemC128>>>(
            Op, m1W + (size_t)l*CH*CCH, m1b + l*CH,
            nullptr, nullptr, nullptr, Mm, Lp,
            m, ps, pq, CH);
        bnred_kernel<<<CH, 32>>>(ps, pq, m1g + l*CH, m1beta + l*CH, scl1, shf1);

        // m2: affine1 on load, stats out
        conv_kernel<64,1,0,true><<<dim3(nT64,1,BB), blk, smemC64>>>(
            m, m2W + (size_t)l*CH*CH, m2b + l*CH,
            scl1, shf1, nullptr, nullptr, nullptr,
            h, ps, pq, CH);
        bnred_kernel<<<CH, 32>>>(ps, pq, m2g + l*CH, m2beta + l*CH, scl2, shf2);

        // m3: affine2 on load, residual = relu(affine_pcn(y)), out -> x
        conv_kernel<64,1,2,false><<<dim3(nT64,2,BB), blk, smemC64>>>(
            h, m3W + (size_t)l*CCH*CH, m3b + l*CCH,
            scl2, shf2, y, scl, shf,
            x, nullptr, nullptr, CCH);
    }

    head_kernel<<<dim3(nT64, BB), 256, smemHead>>>(x, c1W, c1b, c2W, c2b, c3W, c3b, out);
}

// round 14
// speedup vs baseline: 1.5247x; 1.5247x over previous
#include <cuda_runtime.h>
#include <math.h>

#define NPT 3000
#define BB 2
#define CCH 128
#define CH 64
#define LL 6
#define EPSBN 1e-5f
#define ATT_SCALE 0.08838834764831845f  // 1/sqrt(128)

#define TQ 64
#define TI 128
#define ISPLIT 3
#define SPLEN 1000
#define OPAD 3008
#define NEGBIG -1e30f

typedef unsigned long long ull;

__device__ __forceinline__ void ffma2(ull &d, ull a, ull b) {
    asm("fma.rn.f32x2 %0, %1, %2, %0;" : "+l"(d) : "l"(a), "l"(b));
}
__device__ __forceinline__ void mulf2(ull &d, ull f) {
    asm("mul.rn.f32x2 %0, %0, %1;" : "+l"(d) : "l"(f));
}
__device__ __forceinline__ float2 unp(ull v) {
    unsigned lo, hi;
    asm("mov.b64 {%0,%1}, %2;" : "=r"(lo), "=r"(hi) : "l"(v));
    return make_float2(__uint_as_float(lo), __uint_as_float(hi));
}
__device__ __forceinline__ ull packdup(float x) {
    ull r; unsigned u = __float_as_uint(x);
    asm("mov.b64 %0, {%1, %1};" : "=l"(r) : "r"(u));
    return r;
}
__device__ __forceinline__ ull d2u(double d) { return __double_as_longlong(d); }
__device__ __forceinline__ float sqrt_approx(float x) {
    float r; asm("sqrt.approx.f32 %0, %1;" : "=f"(r) : "f"(x)); return r;
}

// ---------------- device scratch ----------------
__device__ float g_x[BB*CCH*NPT];
__device__ float g_y[BB*CCH*NPT];
__device__ float g_v[BB*CCH*NPT];
__device__ float g_m[BB*CCH*NPT];
__device__ float g_h[BB*CCH*NPT];
__device__ float g_qt[(size_t)BB*NPT*CCH];
__device__ float g_kt[(size_t)BB*NPT*CCH];
__device__ float g_Op[(size_t)ISPLIT*BB*CCH*OPAD];
__device__ float g_Lp[ISPLIT*BB*OPAD];
__device__ float g_Mm[ISPLIT*BB*OPAD];
__device__ float g_ps[CCH*64], g_pq[CCH*64];
__device__ float g_scl[CCH],  g_shf[CCH];
__device__ float g_scl1[CCH], g_shf1[CCH];
__device__ float g_scl2[CCH], g_shf2[CCH];

// ---------------- init embedding ----------------
__global__ void init_conv_kernel(const float* __restrict__ corr, const float* __restrict__ W,
                                 const float* __restrict__ bias, float* __restrict__ X)
{
    __shared__ float Ws[CCH*6];
    __shared__ float bs[CCH];
    int tid = threadIdx.x;
    for (int i = tid; i < CCH*6; i += blockDim.x) Ws[i] = W[i];
    for (int i = tid; i < CCH;   i += blockDim.x) bs[i] = bias[i];
    __syncthreads();
    int idx = blockIdx.x * blockDim.x + tid;
    if (idx >= BB*NPT) return;
    int b = idx / NPT, n = idx - b*NPT;
    float cp[6];
#pragma unroll
    for (int j = 0; j < 6; j++) cp[j] = corr[(size_t)idx*6 + j];
    for (int co = 0; co < CCH; co++) {
        float a = bs[co];
#pragma unroll
        for (int j = 0; j < 6; j++) a += Ws[co*6 + j] * cp[j];
        X[((size_t)b*CCH + co)*NPT + n] = a;
    }
}

// ---------------- conv smem ----------------
template<int CIN> struct ConvS {
    float Xs[128][CIN + 4];   // [n][ci], stride ≡ 4 mod 32 -> conflict-free phases
    float Ws[32][CIN + 4];    // [co][ci]
    float sA[CCH], sB[CCH];
    float swc[ISPLIT][128];
};

// ---------------- pointwise conv (warp-broadcast weights, ci-pair packing) ----------------
template<int CIN, int INMODE, int RES, bool STATS>
__global__ void __launch_bounds__(256) conv_kernel(const float* __restrict__ X,
        const float* __restrict__ W, const float* __restrict__ bias,
        const float* __restrict__ scl, const float* __restrict__ shf,
        const float* __restrict__ R, const float* __restrict__ rscl,
        const float* __restrict__ rshf,
        float* __restrict__ Y, float* __restrict__ psum, float* __restrict__ psq,
        int Cout)
{
    extern __shared__ char sraw[];
    ConvS<CIN>& S = *reinterpret_cast<ConvS<CIN>*>(sraw);
    const int tid = threadIdx.x;
    const int b = blockIdx.z, co0 = blockIdx.y << 5, n0 = blockIdx.x << 7;

    if (INMODE == 1) {
        if (tid < CIN) { S.sA[tid] = scl[tid]; S.sB[tid] = shf[tid]; }
    }
    if (INMODE == 3) {
        if (tid < 128) {
            int n = n0 + tid;
            float w0 = 0.f, w1 = 0.f, w2 = 0.f;
            if (n < NPT) {
                float m0 = rscl[(0*BB + b)*OPAD + n];
                float m1v = rscl[(1*BB + b)*OPAD + n];
                float m2v = rscl[(2*BB + b)*OPAD + n];
                float l0 = rshf[(0*BB + b)*OPAD + n];
                float l1 = rshf[(1*BB + b)*OPAD + n];
                float l2 = rshf[(2*BB + b)*OPAD + n];
                float Mx = fmaxf(fmaxf(m0, m1v), m2v);
                w0 = __expf(m0 - Mx); w1 = __expf(m1v - Mx); w2 = __expf(m2v - Mx);
                float inv = 1.f / (l0*w0 + l1*w1 + l2*w2);
                w0 *= inv; w1 *= inv; w2 *= inv;
            }
            S.swc[0][tid] = w0; S.swc[1][tid] = w1; S.swc[2][tid] = w2;
        }
    }
    if (INMODE != 0) __syncthreads();

    // ---- W tile fill [32][CIN] ----
#pragma unroll
    for (int j = 0; j < 32*CIN/1024; j++) {
        int idx = tid + (j << 8);
        int row = idx / (CIN/4), c4 = (idx % (CIN/4)) << 2;
        *(float4*)&S.Ws[row][c4] = *(const float4*)&W[(size_t)(co0 + row)*CIN + c4];
    }
    // ---- X tile fill, transposed to [n][ci] ----
#pragma unroll
    for (int j = 0; j < 128*CIN/1024; j++) {
        int idx = tid + (j << 8);
        int ci = idx & (CIN - 1);
        int n4 = (idx / CIN) << 2;
        float4 v = make_float4(0.f,0.f,0.f,0.f);
        if (n0 + n4 < NPT) {
            if (INMODE == 3) {
                const size_t sstr = (size_t)BB*CCH*OPAD;
                const float* base = X + ((size_t)(b*CCH + ci))*OPAD + n0 + n4;
                float4 a0 = *(const float4*)&base[0];
                float4 a1 = *(const float4*)&base[sstr];
                float4 a2 = *(const float4*)&base[2*sstr];
                v.x = a0.x*S.swc[0][n4]   + a1.x*S.swc[1][n4]   + a2.x*S.swc[2][n4];
                v.y = a0.y*S.swc[0][n4+1] + a1.y*S.swc[1][n4+1] + a2.y*S.swc[2][n4+1];
                v.z = a0.z*S.swc[0][n4+2] + a1.z*S.swc[1][n4+2] + a2.z*S.swc[2][n4+2];
                v.w = a0.w*S.swc[0][n4+3] + a1.w*S.swc[1][n4+3] + a2.w*S.swc[2][n4+3];
            } else {
                v = *(const float4*)&X[((size_t)(b*CIN + ci))*NPT + n0 + n4];
                if (INMODE == 1) {
                    float sa = S.sA[ci], sb = S.sB[ci];
                    v.x = fmaxf(fmaf(sa, v.x, sb), 0.f);
                    v.y = fmaxf(fmaf(sa, v.y, sb), 0.f);
                    v.z = fmaxf(fmaf(sa, v.z, sb), 0.f);
                    v.w = fmaxf(fmaf(sa, v.w, sb), 0.f);
                }
            }
        }
        S.Xs[n4][ci] = v.x; S.Xs[n4+1][ci] = v.y;
        S.Xs[n4+2][ci] = v.z; S.Xs[n4+3][ci] = v.w;
    }
    __syncthreads();

    const int warp = tid >> 5, lane = tid & 31;
    const int r0 = warp << 2;
    ull acc[4][4];
#pragma unroll
    for (int r = 0; r < 4; r++)
#pragma unroll
        for (int s = 0; s < 4; s++) acc[r][s] = 0ull;

#pragma unroll 8
    for (int cq = 0; cq < CIN; cq += 4) {
        double2 wv[4], xv[4];
#pragma unroll
        for (int r = 0; r < 4; r++) wv[r] = *(const double2*)&S.Ws[r0 + r][cq];
#pragma unroll
        for (int s = 0; s < 4; s++) xv[s] = *(const double2*)&S.Xs[lane + (s << 5)][cq];
#pragma unroll
        for (int r = 0; r < 4; r++) {
            ull ax = d2u(wv[r].x), ay = d2u(wv[r].y);
#pragma unroll
            for (int s = 0; s < 4; s++) {
                ffma2(acc[r][s], ax, d2u(xv[s].x));
                ffma2(acc[r][s], ay, d2u(xv[s].y));
            }
        }
    }

    float vals[4][4];
#pragma unroll
    for (int r = 0; r < 4; r++) {
        float bv = bias[co0 + r0 + r];
#pragma unroll
        for (int s = 0; s < 4; s++) {
            float2 f = unp(acc[r][s]);
            vals[r][s] = f.x + f.y + bv;
        }
    }

    if (STATS) {
#pragma unroll
        for (int r = 0; r < 4; r++) {
            float s_ = 0.f, sq = 0.f;
#pragma unroll
            for (int s = 0; s < 4; s++) {
                int n = n0 + lane + (s << 5);
                if (n < NPT) { s_ += vals[r][s]; sq += vals[r][s]*vals[r][s]; }
            }
#pragma unroll
            for (int o = 16; o; o >>= 1) {
                s_ += __shfl_xor_sync(0xffffffffu, s_, o);
                sq += __shfl_xor_sync(0xffffffffu, sq, o);
            }
            if (lane == 0) {
                int co = co0 + r0 + r;
                int p = b*24 + blockIdx.x;
                psum[co*64 + p] = s_;
                psq[co*64 + p]  = sq;
            }
        }
    }

#pragma unroll
    for (int s = 0; s < 4; s++) {
        int n = n0 + lane + (s << 5);
        if (n >= NPT) continue;
#pragma unroll
        for (int r = 0; r < 4; r++) {
            int co = co0 + r0 + r;
            float v = vals[r][s];
            size_t off = ((size_t)(b*Cout + co))*NPT + n;
            if (RES == 2) {
                float rr = R[off];
                v += fmaxf(fmaf(rscl[co], rr, rshf[co]), 0.f);
            }
            Y[off] = v;
        }
    }
}

// ---------------- fused q/k/v conv (576 blocks) ----------------
__global__ void __launch_bounds__(256) qkv_kernel(const float* __restrict__ X,
        const float* __restrict__ qW, const float* __restrict__ kW, const float* __restrict__ vW,
        const float* __restrict__ qb, const float* __restrict__ kb, const float* __restrict__ vb,
        const float* __restrict__ scl, const float* __restrict__ shf,
        float* __restrict__ qt, float* __restrict__ kt, float* __restrict__ v)
{
    extern __shared__ char sraw[];
    ConvS<CCH>& S = *reinterpret_cast<ConvS<CCH>*>(sraw);
    const int tid = threadIdx.x;
    const int sel = blockIdx.y >> 2;
    const float* W    = (sel == 0) ? qW : (sel == 1) ? kW : vW;
    const float* bias = (sel == 0) ? qb : (sel == 1) ? kb : vb;
    const int b = blockIdx.z, co0 = (blockIdx.y & 3) << 5, n0 = blockIdx.x << 7;

    if (tid < CCH) { S.sA[tid] = scl[tid]; S.sB[tid] = shf[tid]; }
    __syncthreads();

#pragma unroll
    for (int j = 0; j < 4; j++) {
        int idx = tid + (j << 8);
        int row = idx >> 5, c4 = (idx & 31) << 2;
        *(float4*)&S.Ws[row][c4] = *(const float4*)&W[(size_t)(co0 + row)*CCH + c4];
    }
#pragma unroll
    for (int j = 0; j < 16; j++) {
        int idx = tid + (j << 8);
        int ci = idx & 127;
        int n4 = (idx >> 7) << 2;
        float4 vv = make_float4(0.f,0.f,0.f,0.f);
        if (n0 + n4 < NPT) {
            vv = *(const float4*)&X[((size_t)(b*CCH + ci))*NPT + n0 + n4];
            float sa = S.sA[ci], sb = S.sB[ci];
            vv.x = fmaxf(fmaf(sa, vv.x, sb), 0.f);
            vv.y = fmaxf(fmaf(sa, vv.y, sb), 0.f);
            vv.z = fmaxf(fmaf(sa, vv.z, sb), 0.f);
            vv.w = fmaxf(fmaf(sa, vv.w, sb), 0.f);
        }
        S.Xs[n4][ci] = vv.x; S.Xs[n4+1][ci] = vv.y;
        S.Xs[n4+2][ci] = vv.z; S.Xs[n4+3][ci] = vv.w;
    }
    __syncthreads();

    const int warp = tid >> 5, lane = tid & 31;
    const int r0 = warp << 2;
    ull acc[4][4];
#pragma unroll
    for (int r = 0; r < 4; r++)
#pragma unroll
        for (int s = 0; s < 4; s++) acc[r][s] = 0ull;

#pragma unroll 8
    for (int cq = 0; cq < CCH; cq += 4) {
        double2 wv[4], xv[4];
#pragma unroll
        for (int r = 0; r < 4; r++) wv[r] = *(const double2*)&S.Ws[r0 + r][cq];
#pragma unroll
        for (int s = 0; s < 4; s++) xv[s] = *(const double2*)&S.Xs[lane + (s << 5)][cq];
#pragma unroll
        for (int r = 0; r < 4; r++) {
            ull ax = d2u(wv[r].x), ay = d2u(wv[r].y);
#pragma unroll
            for (int s = 0; s < 4; s++) {
                ffma2(acc[r][s], ax, d2u(xv[s].x));
                ffma2(acc[r][s], ay, d2u(xv[s].y));
            }
        }
    }

    float vals[4][4];
#pragma unroll
    for (int r = 0; r < 4; r++) {
        float bv = bias[co0 + r0 + r];
#pragma unroll
        for (int s = 0; s < 4; s++) {
            float2 f = unp(acc[r][s]);
            vals[r][s] = f.x + f.y + bv;
        }
    }

    if (sel < 2) {
        float* base = ((sel == 0) ? qt : kt) + (size_t)b*NPT*CCH;
#pragma unroll
        for (int s = 0; s < 4; s++) {
            int n = n0 + lane + (s << 5);
            if (n >= NPT) continue;
            *(float4*)&base[(size_t)n*CCH + co0 + r0] =
                make_float4(vals[0][s], vals[1][s], vals[2][s], vals[3][s]);
        }
    } else {
#pragma unroll
        for (int s = 0; s < 4; s++) {
            int n = n0 + lane + (s << 5);
            if (n >= NPT) continue;
#pragma unroll
            for (int r = 0; r < 4; r++)
                v[((size_t)(b*CCH + co0 + r0 + r))*NPT + n] = vals[r][s];
        }
    }
}

// ---------------- partial-sum reduce -> per-channel affine ----------------
__global__ void bnred_kernel(const float* __restrict__ psum, const float* __restrict__ psq,
                             const float* __restrict__ g, const float* __restrict__ beta,
                             float* __restrict__ scl, float* __restrict__ shf)
{
    int c = blockIdx.x, t = threadIdx.x;
    float s = 0.f, q = 0.f;
    for (int p = t; p < 48; p += 32) { s += psum[c*64 + p]; q += psq[c*64 + p]; }
#pragma unroll
    for (int o = 16; o; o >>= 1) {
        s += __shfl_xor_sync(0xffffffffu, s, o);
        q += __shfl_xor_sync(0xffffffffu, q, o);
    }
    if (t == 0) {
        float inv = 1.f / (float)(BB*NPT);
        float m = s * inv;
        float var = q * inv - m*m;
        float rs = rsqrtf(var + EPSBN);
        scl[c] = g[c] * rs;
        shf[c] = beta[c] - m * g[c] * rs;
    }
}

// ---------------- flash attention (unchanged, proven) ----------------
struct FlashS {
    float Qt[TQ][132];
    float KV[CCH*132];
    float Pd[TQ][132];
    float pOs[TQ][6];
    float pI[TI][6];
    float alph[TQ];
};

__global__ void __launch_bounds__(512, 1) flash_kernel(
    const float* __restrict__ Qt, const float* __restrict__ Kt,
    const float* __restrict__ V,
    const float* __restrict__ src, const float* __restrict__ tgt,
    float* __restrict__ Op, float* __restrict__ Lp, float* __restrict__ Mm)
{
    extern __shared__ char smem_raw[];
    FlashS& S = *reinterpret_cast<FlashS*>(smem_raw);
    int tid = threadIdx.x;
    int otile = blockIdx.x * TQ;
    int sp = blockIdx.y, b = blockIdx.z;
    int sbase = sp * SPLEN;
    int send  = min(sbase + SPLEN, NPT);
    int warp = tid >> 5, lane = tid & 31;
    int o0 = warp << 2;
    int c0 = warp << 3;

#pragma unroll
    for (int j = 0; j < 4; j++) {
        int idx = tid + (j << 9);
        int row = idx >> 5, c4 = (idx & 31) << 2;
        int go = otile + row;
        float4 qv = make_float4(0.f,0.f,0.f,0.f);
        if (go < NPT) qv = *(const float4*)&Qt[((size_t)b*NPT + go)*CCH + c4];
        *(float4*)&S.Qt[row][c4] = qv;
    }
    if (tid < TQ) {
        int go = otile + tid;
        if (go < NPT) {
#pragma unroll
            for (int e = 0; e < 3; e++) {
                S.pOs[tid][e]   = src[((size_t)b*NPT + go)*3 + e];
                S.pOs[tid][3+e] = tgt[((size_t)b*NPT + go)*3 + e];
            }
        } else {
#pragma unroll
            for (int e = 0; e < 6; e++) S.pOs[tid][e] = 0.f;
        }
    }
    float mr[4] = {NEGBIG, NEGBIG, NEGBIG, NEGBIG};
    float lr[4] = {0.f, 0.f, 0.f, 0.f};
    ull accO[8][2];
#pragma unroll
    for (int i = 0; i < 8; i++) { accO[i][0] = 0ull; accO[i][1] = 0ull; }

    const int nch = (send - sbase + TI - 1) / TI;
#pragma unroll 1
    for (int ch = 0; ch < nch; ch++) {
        int ibase = sbase + ch * TI;
        __syncthreads();
#pragma unroll
        for (int j = 0; j < 8; j++) {
            int idx = tid + (j << 9);
            int row = idx >> 5, c4 = (idx & 31) << 2;
            int gi = ibase + row;
            float4 kv = make_float4(0.f,0.f,0.f,0.f);
            if (gi < send) kv = *(const float4*)&Kt[((size_t)b*NPT + gi)*CCH + c4];
            *(float4*)&S.KV[row*132 + c4] = kv;
        }
        if (tid < TI) {
            int gi = ibase + tid;
            if (gi < send) {
#pragma unroll
                for (int e = 0; e < 3; e++) {
                    S.pI[tid][e]   = src[((size_t)b*NPT + gi)*3 + e];
                    S.pI[tid][3+e] = tgt[((size_t)b*NPT + gi)*3 + e];
                }
            } else {
#pragma unroll
                for (int e = 0; e < 6; e++) S.pI[tid][e] = 0.f;
            }
        }
        __syncthreads();

        ull sacc[4][4];
#pragma unroll
        for (int r = 0; r < 4; r++)
#pragma unroll
            for (int s = 0; s < 4; s++) sacc[r][s] = 0ull;
#pragma unroll 4
        for (int cq = 0; cq < CCH; cq += 4) {
            double2 qv[4], kv[4];
#pragma unroll
            for (int r = 0; r < 4; r++) qv[r] = *(const double2*)&S.Qt[o0 + r][cq];
#pragma unroll
            for (int s = 0; s < 4; s++) kv[s] = *(const double2*)&S.KV[(lane + (s << 5))*132 + cq];
#pragma unroll
            for (int r = 0; r < 4; r++) {
                ull ax = d2u(qv[r].x), ay = d2u(qv[r].y);
#pragma unroll
                for (int s = 0; s < 4; s++) {
                    ffma2(sacc[r][s], ax, d2u(kv[s].x));
                    ffma2(sacc[r][s], ay, d2u(kv[s].y));
                }
            }
        }

        float sv[4][4];
#pragma unroll
        for (int r = 0; r < 4; r++)
#pragma unroll
            for (int s = 0; s < 4; s++) {
                float2 f = unp(sacc[r][s]);
                sv[r][s] = f.x + f.y;
            }
#pragma unroll
        for (int s = 0; s < 4; s++) {
            int il = lane + (s << 5);
            bool valid = (ibase + il) < send;
            float pi0 = S.pI[il][0], pi1 = S.pI[il][1], pi2 = S.pI[il][2];
            float pi3 = S.pI[il][3], pi4 = S.pI[il][4], pi5 = S.pI[il][5];
#pragma unroll
            for (int r = 0; r < 4; r++) {
                float dx = S.pOs[o0+r][0] - pi0, dy = S.pOs[o0+r][1] - pi1, dz = S.pOs[o0+r][2] - pi2;
                float ds = sqrt_approx(dx*dx + dy*dy + dz*dz);
                dx = S.pOs[o0+r][3] - pi3; dy = S.pOs[o0+r][4] - pi4; dz = S.pOs[o0+r][5] - pi5;
                float dt = sqrt_approx(dx*dx + dy*dy + dz*dz);
                float d = ds - dt;
                float scv = fmaxf(1.f - d*d, 0.f) * ATT_SCALE;
                sv[r][s] = valid ? sv[r][s] * scv : NEGBIG;
            }
        }
#pragma unroll
        for (int r = 0; r < 4; r++) {
            float mx = fmaxf(fmaxf(sv[r][0], sv[r][1]), fmaxf(sv[r][2], sv[r][3]));
#pragma unroll
            for (int s = 16; s; s >>= 1) mx = fmaxf(mx, __shfl_xor_sync(0xffffffffu, mx, s));
            float mnew = fmaxf(mr[r], mx);
            float al = __expf(mr[r] - mnew);
            mr[r] = mnew;
            float psum = 0.f;
#pragma unroll
            for (int s = 0; s < 4; s++) {
                float p = __expf(sv[r][s] - mnew);
                S.Pd[o0 + r][lane + (s << 5)] = p;
                psum += p;
            }
#pragma unroll
            for (int s = 16; s; s >>= 1) psum += __shfl_xor_sync(0xffffffffu, psum, s);
            lr[r] = lr[r] * al + psum;
            if (lane == 0) S.alph[o0 + r] = al;
        }
        __syncthreads();

#pragma unroll
        for (int j = 0; j < 8; j++) {
            int idx = tid + (j << 9);
            int row = idx >> 5, i4 = (idx & 31) << 2;
            int gi = ibase + i4;
            float4 vv = make_float4(0.f,0.f,0.f,0.f);
            if (gi < send) vv = *(const float4*)&V[((size_t)(b*CCH + row))*NPT + gi];
            *(float4*)&S.KV[row*132 + i4] = vv;
        }
        __syncthreads();

        {
            ull ad0 = packdup(S.alph[lane]);
            ull ad1 = packdup(S.alph[lane + 32]);
#pragma unroll
            for (int cc = 0; cc < 8; cc++) { mulf2(accO[cc][0], ad0); mulf2(accO[cc][1], ad1); }
        }
#pragma unroll 2
        for (int iq = 0; iq < TI; iq += 4) {
            double2 b0 = *(const double2*)&S.Pd[lane][iq];
            double2 b1 = *(const double2*)&S.Pd[lane + 32][iq];
            ull b0x = d2u(b0.x), b0y = d2u(b0.y), b1x = d2u(b1.x), b1y = d2u(b1.y);
#pragma unroll
            for (int cc = 0; cc < 8; cc++) {
                double2 av = *(const double2*)&S.KV[(c0 + cc)*132 + iq];
                ull ax = d2u(av.x), ay = d2u(av.y);
                ffma2(accO[cc][0], ax, b0x);
                ffma2(accO[cc][0], ay, b0y);
                ffma2(accO[cc][1], ax, b1x);
                ffma2(accO[cc][1], ay, b1y);
            }
        }
    }

#pragma unroll
    for (int cc = 0; cc < 8; cc++)
#pragma unroll
        for (int ok = 0; ok < 2; ok++) {
            float2 f = unp(accO[cc][ok]);
            float val = f.x + f.y;
            int go = otile + lane + (ok << 5);
            if (go < NPT)
                Op[((size_t)((sp*BB + b)*CCH + c0 + cc))*OPAD + go] = val;
        }
    if (lane == 0) {
#pragma unroll
        for (int r = 0; r < 4; r++) {
            int go = otile + o0 + r;
            if (go < NPT) {
                Mm[(sp*BB + b)*OPAD + go] = mr[r];
                Lp[(sp*BB + b)*OPAD + go] = lr[r];
            }
        }
    }
}

// ---------------- fused head: norm + c1 + c2 + c3 ----------------
struct HeadS {
    float xt[CCH][68];
    float cw1[32][128];
    float cw2[32][32];
    float cw3[32];
    float b1[32], b2[32];
    float ph1[64][33];
    float ph2[64][33];
    float sinv[64];
};

__global__ void __launch_bounds__(256) head_kernel(const float* __restrict__ X,
        const float* __restrict__ c1W, const float* __restrict__ c1b,
        const float* __restrict__ c2W, const float* __restrict__ c2b,
        const float* __restrict__ c3W, const float* __restrict__ c3b,
        float* __restrict__ out)
{
    extern __shared__ char sraw[];
    HeadS& S = *reinterpret_cast<HeadS*>(sraw);
    int tid = threadIdx.x;
    int n0 = blockIdx.x << 6, b = blockIdx.y;

    for (int i = tid; i < 32*128; i += 256) S.cw1[i >> 7][i & 127] = c1W[i];
    for (int i = tid; i < 32*32;  i += 256) S.cw2[i >> 5][i & 31]  = c2W[i];
    if (tid < 32) { S.cw3[tid] = c3W[tid]; S.b1[tid] = c1b[tid]; S.b2[tid] = c2b[tid]; }
    for (int t = tid; t < CCH*16; t += 256) {
        int row = t >> 4, j4 = (t & 15) << 2;
        float4 v = make_float4(0.f,0.f,0.f,0.f);
        if (n0 + j4 < NPT) v = *(const float4*)&X[((size_t)(b*CCH + row))*NPT + n0 + j4];
        *(float4*)&S.xt[row][j4] = v;
    }
    __syncthreads();

    int p = tid >> 2, qd = tid & 3;
    float ss = 0.f;
    for (int c = qd*32; c < qd*32 + 32; c++) { float v = S.xt[c][p]; ss += v*v; }
    ss += __shfl_xor_sync(0xffffffffu, ss, 1, 4);
    ss += __shfl_xor_sync(0xffffffffu, ss, 2, 4);
    if (qd == 0) S.sinv[p] = 1.f / fmaxf(sqrtf(ss), 1e-12f);

#pragma unroll
    for (int jj = 0; jj < 8; jj++) {
        int j = qd*8 + jj;
        float a = S.b1[j];
        for (int c = 0; c < CCH; c++) a += S.cw1[j][c] * S.xt[c][p];
        S.ph1[p][j] = fmaxf(a, 0.f);
    }
    __syncthreads();
#pragma unroll
    for (int jj = 0; jj < 8; jj++) {
        int j = qd*8 + jj;
        float a = S.b2[j];
        for (int c = 0; c < 32; c++) a += S.cw2[j][c] * S.ph1[p][c];
        S.ph2[p][j] = fmaxf(a, 0.f);
    }
    __syncthreads();
    if (qd == 0) {
        float a = c3b[0];
        for (int c = 0; c < 32; c++) a += S.cw3[c] * S.ph2[p][c];
        int n = n0 + p;
        if (n < NPT) out[b*NPT + n] = a;
    }
    float* dst = out + BB*NPT;
    for (int t = tid; t < CCH*16; t += 256) {
        int row = t >> 4, j4 = (t & 15) << 2;
#pragma unroll
        for (int e = 0; e < 4; e++) {
            int n = n0 + j4 + e;
            if (n < NPT)
                dst[((size_t)(b*CCH + row))*NPT + n] = S.xt[row][j4 + e] * S.sinv[j4 + e];
        }
    }
}

// ======================= host launcher =======================
extern "C" void kernel_launch(void* const* d_in, const int* in_sizes, int n_in,
                              void* d_out, int out_size)
{
    const float* corr    = (const float*)d_in[0];
    const float* src     = (const float*)d_in[1];
    const float* tgt     = (const float*)d_in[2];
    const float* iW      = (const float*)d_in[3];
    const float* ib      = (const float*)d_in[4];
    const float* pcnW    = (const float*)d_in[5];
    const float* pcnb    = (const float*)d_in[6];
    const float* pcng    = (const float*)d_in[7];
    const float* pcnbeta = (const float*)d_in[8];
    const float* qW  = (const float*)d_in[9];  const float* qb  = (const float*)d_in[10];
    const float* kW  = (const float*)d_in[11]; const float* kb  = (const float*)d_in[12];
    const float* vW  = (const float*)d_in[13]; const float* vb  = (const float*)d_in[14];
    const float* m1W = (const float*)d_in[15]; const float* m1b = (const float*)d_in[16];
    const float* m1g = (const float*)d_in[17]; const float* m1beta = (const float*)d_in[18];
    const float* m2W = (const float*)d_in[19]; const float* m2b = (const float*)d_in[20];
    const float* m2g = (const float*)d_in[21]; const float* m2beta = (const float*)d_in[22];
    const float* m3W = (const float*)d_in[23]; const float* m3b = (const float*)d_in[24];
    const float* c1W = (const float*)d_in[25]; const float* c1b = (const float*)d_in[26];
    const float* c2W = (const float*)d_in[27]; const float* c2b = (const float*)d_in[28];
    const float* c3W = (const float*)d_in[29]; const float* c3b = (const float*)d_in[30];
    float* out = (float*)d_out;

    float *x, *y, *v, *m, *h, *qt, *kt, *Op, *Lp, *Mm, *ps, *pq;
    float *scl, *shf, *scl1, *shf1, *scl2, *shf2;
    cudaGetSymbolAddress((void**)&x,  g_x);
    cudaGetSymbolAddress((void**)&y,  g_y);
    cudaGetSymbolAddress((void**)&v,  g_v);
    cudaGetSymbolAddress((void**)&m,  g_m);
    cudaGetSymbolAddress((void**)&h,  g_h);
    cudaGetSymbolAddress((void**)&qt, g_qt);
    cudaGetSymbolAddress((void**)&kt, g_kt);
    cudaGetSymbolAddress((void**)&Op, g_Op);
    cudaGetSymbolAddress((void**)&Lp, g_Lp);
    cudaGetSymbolAddress((void**)&Mm, g_Mm);
    cudaGetSymbolAddress((void**)&ps, g_ps);
    cudaGetSymbolAddress((void**)&pq, g_pq);
    cudaGetSymbolAddress((void**)&scl,  g_scl);  cudaGetSymbolAddress((void**)&shf,  g_shf);
    cudaGetSymbolAddress((void**)&scl1, g_scl1); cudaGetSymbolAddress((void**)&shf1, g_shf1);
    cudaGetSymbolAddress((void**)&scl2, g_scl2); cudaGetSymbolAddress((void**)&shf2, g_shf2);

    const int nT64  = (NPT + 63) / 64;    // 47 (flash / head)
    const int nT128 = (NPT + 127) / 128;  // 24 (convs)
    const int smemC128 = (int)sizeof(ConvS<128>);
    const int smemC64  = (int)sizeof(ConvS<64>);
    const int smemFlash = (int)sizeof(FlashS);
    const int smemHead  = (int)sizeof(HeadS);
    cudaFuncSetAttribute(conv_kernel<128,0,0,true>, cudaFuncAttributeMaxDynamicSharedMemorySize, smemC128);
    cudaFuncSetAttribute(conv_kernel<128,3,0,true>, cudaFuncAttributeMaxDynamicSharedMemorySize, smemC128);
    cudaFuncSetAttribute(conv_kernel<64,1,0,true>,  cudaFuncAttributeMaxDynamicSharedMemorySize, smemC64);
    cudaFuncSetAttribute(conv_kernel<64,1,2,false>, cudaFuncAttributeMaxDynamicSharedMemorySize, smemC64);
    cudaFuncSetAttribute(qkv_kernel, cudaFuncAttributeMaxDynamicSharedMemorySize, smemC128);
    cudaFuncSetAttribute(flash_kernel, cudaFuncAttributeMaxDynamicSharedMemorySize, smemFlash);
    cudaFuncSetAttribute(head_kernel,  cudaFuncAttributeMaxDynamicSharedMemorySize, smemHead);
    // NEW: request max shared-memory carveout so two 87KB conv blocks can co-reside
    cudaFuncSetAttribute(conv_kernel<128,0,0,true>, cudaFuncAttributePreferredSharedMemoryCarveout, 100);
    cudaFuncSetAttribute(conv_kernel<128,3,0,true>, cudaFuncAttributePreferredSharedMemoryCarveout, 100);
    cudaFuncSetAttribute(conv_kernel<64,1,0,true>,  cudaFuncAttributePreferredSharedMemoryCarveout, 100);
    cudaFuncSetAttribute(conv_kernel<64,1,2,false>, cudaFuncAttributePreferredSharedMemoryCarveout, 100);
    cudaFuncSetAttribute(qkv_kernel, cudaFuncAttributePreferredSharedMemoryCarveout, 100);

    dim3 blk(256);
    init_conv_kernel<<<(BB*NPT + 127)/128, 128>>>(corr, iW, ib, x);

    for (int l = 0; l < LL; l++) {
        // PointCN conv (pre-BN output y) + stats partials
        conv_kernel<128,0,0,true><<<dim3(nT128,4,BB), blk, smemC128>>>(
            x, pcnW + (size_t)l*CCH*CCH, pcnb + l*CCH,
            nullptr, nullptr, nullptr, nullptr, nullptr,
            y, ps, pq, CCH);
        bnred_kernel<<<CCH, 32>>>(ps, pq, pcng + l*CCH, pcnbeta + l*CCH, scl, shf);

        // fused q/k/v (576 blocks; affine+relu on load; q,k transposed out)
        qkv_kernel<<<dim3(nT128,12,BB), blk, smemC128>>>(
            y, qW + (size_t)l*CCH*CCH, kW + (size_t)l*CCH*CCH, vW + (size_t)l*CCH*CCH,
            qb + l*CCH, kb + l*CCH, vb + l*CCH, scl, shf, qt, kt, v);

        // flash attention
        flash_kernel<<<dim3(nT64, ISPLIT, BB), 512, smemFlash>>>(qt, kt, v, src, tgt, Op, Lp, Mm);

        // m1: merge partials on load (weights from Mm/Lp), stats out
        conv_kernel<128,3,0,true><<<dim3(nT128,2,BB), blk, smemC128>>>(
            Op, m1W + (size_t)l*CH*CCH, m1b + l*CH,
            nullptr, nullptr, nullptr, Mm, Lp,
            m, ps, pq, CH);
        bnred_kernel<<<CH, 32>>>(ps, pq, m1g + l*CH, m1beta + l*CH, scl1, shf1);

        // m2: affine1 on load, stats out
        conv_kernel<64,1,0,true><<<dim3(nT128,2,BB), blk, smemC64>>>(
            m, m2W + (size_t)l*CH*CH, m2b + l*CH,
            scl1, shf1, nullptr, nullptr, nullptr,
            h, ps, pq, CH);
        bnred_kernel<<<CH, 32>>>(ps, pq, m2g + l*CH, m2beta + l*CH, scl2, shf2);

        // m3: affine2 on load, residual = relu(affine_pcn(y)), out -> x
        conv_kernel<64,1,2,false><<<dim3(nT128,4,BB), blk, smemC64>>>(
            h, m3W + (size_t)l*CCH*CH, m3b + l*CCH,
            scl2, shf2, y, scl, shf,
            x, nullptr, nullptr, CCH);
    }

    head_kernel<<<dim3(nT64, BB), 256, smemHead>>>(x, c1W, c1b, c2W, c2b, c3W, c3b, out);
}